// round 2
// baseline (speedup 1.0000x reference)
#include <cuda_runtime.h>
#include <math.h>
#include <stdint.h>

#define D32   32
#define OD    16
#define NB    4
#define KK    32
#define R2C   0.09f
#define EPSF  1e-5f
#define NMAX  100000
#define IC    128
#define MR    (IC*IC)

// ---------------- device scratch (no allocations allowed) ----------------
__device__ float g_yA[NMAX*64];
__device__ float g_yB[NMAX*64];
__device__ float g_maskf[NMAX*OD];
__device__ float g_kernf[NMAX*OD];
__device__ float g_stats[3*128];    // towers: [layer*128 + c] = sum, [+64] = sumsq
__device__ float g_mstats[3*128];   // merge tower, 35 cols used
__device__ int   g_topk[IC];
__device__ float g_weights[IC*337];
__device__ float g_feat[IC*35];
__device__ float g_ctr[IC*3];
__device__ int   g_cb[IC];
__device__ float g_mA[MR*35];
__device__ float g_mB[MR*35];
__device__ float g_nmsbuf[NMAX];

__device__ __forceinline__ float sigmoidf_(float x) {
    return 1.0f / (1.0f + __expf(-x));
}

// ---------------- init: zero stat accumulators (graph replays need this) ----------------
__global__ void init_kernel() {
    int t = threadIdx.x;
    if (t < 384) { g_stats[t] = 0.f; g_mstats[t] = 0.f; }
}

// ---------------- greedy top-K NMS, one block per batch, heat staged in L2 ----------------
__global__ __launch_bounds__(1024, 1)
void nms_kernel(const float* __restrict__ heat, const float* __restrict__ coords,
                const int* __restrict__ bidx, int N) {
    int b = blockIdx.x;
    // binary search batch range [s, e)
    int lo = 0, hi = N;
    while (lo < hi) { int m = (lo + hi) >> 1; if (bidx[m] < b) lo = m + 1; else hi = m; }
    int s = lo; hi = N;
    while (lo < hi) { int m = (lo + hi) >> 1; if (bidx[m] <= b) lo = m + 1; else hi = m; }
    int e = lo, nb = e - s;

    float* buf = g_nmsbuf + s;
    for (int t = threadIdx.x; t < nb; t += 1024) buf[t] = heat[s + t];

    __shared__ float rv[32]; __shared__ int ri[32];
    __shared__ float cc[3]; __shared__ int have;
    if (threadIdx.x == 0) have = 0;
    __syncthreads();

    const float NEG = __int_as_float(0xff800000);
    int lane = threadIdx.x & 31, w = threadIdx.x >> 5;

    for (int k = 0; k < KK; k++) {
        int h = have;
        float cx = 0.f, cy = 0.f, cz = 0.f;
        if (h) { cx = cc[0]; cy = cc[1]; cz = cc[2]; }
        float best = NEG; int bi = 0x7fffffff;
        for (int t = threadIdx.x; t < nb; t += 1024) {
            float v = buf[t];
            if (h && v != NEG) {
                int g = s + t;
                float dx = coords[g*3]   - cx;
                float dy = coords[g*3+1] - cy;
                float dz = coords[g*3+2] - cz;
                if (dx*dx + dy*dy + dz*dz < R2C) { v = NEG; buf[t] = NEG; }
            }
            if (v > best) { best = v; bi = t; }   // strict >, ascending t => first max
        }
        #pragma unroll
        for (int o = 16; o; o >>= 1) {
            float ov = __shfl_down_sync(0xffffffffu, best, o);
            int   oi = __shfl_down_sync(0xffffffffu, bi, o);
            if (ov > best || (ov == best && oi < bi)) { best = ov; bi = oi; }
        }
        if (lane == 0) { rv[w] = best; ri[w] = bi; }
        __syncthreads();
        if (w == 0) {
            best = rv[lane]; bi = ri[lane];
            #pragma unroll
            for (int o = 16; o; o >>= 1) {
                float ov = __shfl_down_sync(0xffffffffu, best, o);
                int   oi = __shfl_down_sync(0xffffffffu, bi, o);
                if (ov > best || (ov == best && oi < bi)) { best = ov; bi = oi; }
            }
            if (lane == 0) {
                int chosen = (best == NEG) ? 0 : (s + bi);   // jnp.argmax(all -inf) == 0
                g_topk[b*KK + k] = chosen;
                cc[0] = coords[chosen*3]; cc[1] = coords[chosen*3+1]; cc[2] = coords[chosen*3+2];
                have = 1;
            }
        }
        __syncthreads();
    }
}

// ---------------- one tower layer for BOTH towers, two-phase (low register pressure) ----------------
// y[:, 0:32]  = bnrelu(x_m) @ Wml ;  y[:, 32:64] = bnrelu(x_k) @ Wkl
__global__ __launch_bounds__(128, 1)
void tower_layer_kernel(const float* __restrict__ x, float* __restrict__ y,
                        const float* __restrict__ Wml, const float* __restrict__ Wkl,
                        const float* __restrict__ pstats, float* __restrict__ ostats,
                        int N, int layer0) {
    __shared__ float Ws[32*64];      // [d][ j<32: m, j>=32: k ]
    __shared__ float smean[64], srstd[64];
    __shared__ float ps[4][128];
    for (int t = threadIdx.x; t < 2048; t += 128) {
        int d = t >> 6, j = t & 63;
        Ws[t] = (j < 32) ? Wml[d*32 + j] : Wkl[d*32 + (j - 32)];
    }
    if (!layer0 && threadIdx.x < 64) {
        float s = pstats[threadIdx.x], q = pstats[64 + threadIdx.x];
        float m = s / (float)N;
        float v = q / (float)N - m*m;
        smean[threadIdx.x] = m;
        srstd[threadIdx.x] = rsqrtf(v + EPSF);
    }
    __syncthreads();

    int n = blockIdx.x * 128 + threadIdx.x;
    int lane = threadIdx.x & 31, warp = threadIdx.x >> 5;
    int instr = (layer0 ? 32 : 64);

    #pragma unroll
    for (int half = 0; half < 2; half++) {
        float xv[32];
        float acc[32];
        #pragma unroll
        for (int j = 0; j < 32; j++) acc[j] = 0.f;

        if (n < N) {
            int coff = layer0 ? 0 : half * 32;
            const float4* xr = (const float4*)(x + (size_t)n * instr + coff);
            if (layer0) {
                #pragma unroll
                for (int q = 0; q < 8; q++) {
                    float4 v = xr[q]; int d = q*4;
                    xv[d] = v.x; xv[d+1] = v.y; xv[d+2] = v.z; xv[d+3] = v.w;
                }
            } else {
                #pragma unroll
                for (int q = 0; q < 8; q++) {
                    float4 v = xr[q]; int d = q*4; int c = coff + d;
                    xv[d]   = fmaxf((v.x - smean[c])   * srstd[c],   0.f);
                    xv[d+1] = fmaxf((v.y - smean[c+1]) * srstd[c+1], 0.f);
                    xv[d+2] = fmaxf((v.z - smean[c+2]) * srstd[c+2], 0.f);
                    xv[d+3] = fmaxf((v.w - smean[c+3]) * srstd[c+3], 0.f);
                }
            }
            #pragma unroll 4
            for (int d = 0; d < 32; d++) {
                float xa = xv[d];
                const float4* w4 = (const float4*)(Ws + d*64 + half*32);
                #pragma unroll
                for (int q = 0; q < 8; q++) {
                    float4 w = w4[q]; int j = q*4;
                    acc[j]   = fmaf(xa, w.x, acc[j]);
                    acc[j+1] = fmaf(xa, w.y, acc[j+1]);
                    acc[j+2] = fmaf(xa, w.z, acc[j+2]);
                    acc[j+3] = fmaf(xa, w.w, acc[j+3]);
                }
            }
            float4* yr = (float4*)(y + (size_t)n * 64 + half*32);
            #pragma unroll
            for (int q = 0; q < 8; q++) {
                float4 v; int j = q*4;
                v.x = acc[j]; v.y = acc[j+1]; v.z = acc[j+2]; v.w = acc[j+3];
                yr[q] = v;
            }
        }
        // per-column sums into smem partials (all threads participate; acc=0 when n>=N)
        #pragma unroll 8
        for (int c = 0; c < 32; c++) {
            float s = acc[c]; float q = s * s;
            #pragma unroll
            for (int o = 16; o; o >>= 1) {
                s += __shfl_down_sync(0xffffffffu, s, o);
                q += __shfl_down_sync(0xffffffffu, q, o);
            }
            if (lane == 0) { ps[warp][half*32 + c] = s; ps[warp][64 + half*32 + c] = q; }
        }
    }
    __syncthreads();
    {
        float t = ps[0][threadIdx.x] + ps[1][threadIdx.x] + ps[2][threadIdx.x] + ps[3][threadIdx.x];
        atomicAdd(&ostats[threadIdx.x], t);
    }
}

// ---------------- final projection: mask_feats, kernel_feats ----------------
__global__ __launch_bounds__(128, 1)
void feats_kernel(const float* __restrict__ yin,
                  const float* __restrict__ Wmo, const float* __restrict__ bmo,
                  const float* __restrict__ Wko, const float* __restrict__ bko,
                  const float* __restrict__ pstats, int N) {
    __shared__ float Wos[32*32];   // [d][ j<16: m-tower, j>=16: k-tower ]
    __shared__ float bs[32];
    __shared__ float smean[64], srstd[64];
    for (int t = threadIdx.x; t < 1024; t += 128) {
        int d = t >> 5, j = t & 31;
        Wos[t] = (j < 16) ? Wmo[d*16 + j] : Wko[d*16 + (j - 16)];
    }
    if (threadIdx.x < 32) bs[threadIdx.x] = (threadIdx.x < 16) ? bmo[threadIdx.x] : bko[threadIdx.x - 16];
    if (threadIdx.x < 64) {
        float s = pstats[threadIdx.x], q = pstats[64 + threadIdx.x];
        float m = s / (float)N;
        float v = q / (float)N - m*m;
        smean[threadIdx.x] = m; srstd[threadIdx.x] = rsqrtf(v + EPSF);
    }
    __syncthreads();
    int n = blockIdx.x * 128 + threadIdx.x;
    if (n >= N) return;

    // two halves sequentially (m then k) to keep registers low
    #pragma unroll
    for (int half = 0; half < 2; half++) {
        float xv[32];
        const float4* xr = (const float4*)(yin + (size_t)n * 64 + half*32);
        #pragma unroll
        for (int q = 0; q < 8; q++) {
            float4 v = xr[q]; int d = q*4; int c = half*32 + d;
            xv[d]   = fmaxf((v.x - smean[c])   * srstd[c],   0.f);
            xv[d+1] = fmaxf((v.y - smean[c+1]) * srstd[c+1], 0.f);
            xv[d+2] = fmaxf((v.z - smean[c+2]) * srstd[c+2], 0.f);
            xv[d+3] = fmaxf((v.w - smean[c+3]) * srstd[c+3], 0.f);
        }
        float acc[16];
        #pragma unroll
        for (int j = 0; j < 16; j++) acc[j] = 0.f;
        #pragma unroll 4
        for (int d = 0; d < 32; d++) {
            float xa = xv[d];
            const float4* w4 = (const float4*)(Wos + d*32 + half*16);
            #pragma unroll
            for (int q = 0; q < 4; q++) {
                float4 w = w4[q]; int j = q*4;
                acc[j]   = fmaf(xa, w.x, acc[j]);
                acc[j+1] = fmaf(xa, w.y, acc[j+1]);
                acc[j+2] = fmaf(xa, w.z, acc[j+2]);
                acc[j+3] = fmaf(xa, w.w, acc[j+3]);
            }
        }
        float* dst = half ? (g_kernf + (size_t)n * 16) : (g_maskf + (size_t)n * 16);
        float4* o4 = (float4*)dst;
        #pragma unroll
        for (int q = 0; q < 4; q++) {
            float4 v; int j = q*4; int bj = half*16 + j;
            v.x = acc[j] + bs[bj]; v.y = acc[j+1] + bs[bj+1];
            v.z = acc[j+2] + bs[bj+2]; v.w = acc[j+3] + bs[bj+3];
            o4[q] = v;
        }
    }
}

// ---------------- candidate gather + weight generator (128 blocks) ----------------
__global__ void cand_prep_kernel(const float* __restrict__ coords, const int* __restrict__ bidx,
                                 const float* __restrict__ Wwg, const float* __restrict__ bwg) {
    int i = blockIdx.x;
    int tid = threadIdx.x;
    __shared__ float ck[16];
    __shared__ int sidx;
    if (tid == 0) sidx = g_topk[i];
    __syncthreads();
    int idx = sidx;
    if (tid < 16) {
        float v = g_kernf[(size_t)idx*16 + tid];
        ck[tid] = v;
        g_feat[i*35 + tid] = v;
    } else if (tid < 32) {
        g_feat[i*35 + tid] = g_maskf[(size_t)idx*16 + (tid - 16)];
    } else if (tid < 35) {
        float c = coords[(size_t)idx*3 + (tid - 32)];
        g_feat[i*35 + tid] = c;
        g_ctr[i*3 + (tid - 32)] = c;
    } else if (tid == 35) {
        g_cb[i] = bidx[idx];
    }
    __syncthreads();
    if (tid < 337) {
        float w = bwg[tid];
        #pragma unroll
        for (int d = 0; d < 16; d++) w = fmaf(ck[d], Wwg[d*337 + tid], w);
        g_weights[i*337 + tid] = w;
    }
}

// ---------------- dynamic mask head: the big one ----------------
__global__ __launch_bounds__(256, 1)
void masks_kernel(const float* __restrict__ coords, float* __restrict__ out, int N) {
    // 32 candidates per block (blockIdx.y), 256 points per block (blockIdx.x)
    __shared__ float w1t[32*16*20];  // [ci][j][d0..18], padded to 20 (80B, 16B-aligned)
    __shared__ float b1s[32*16];
    __shared__ float w2s[32*16];
    __shared__ float b2s[32];
    __shared__ float ctrs[32*3];
    int ibase = blockIdx.y * 32;
    int tid = threadIdx.x;

    for (int t = tid; t < 32*304; t += 256) {
        int ci = t / 304, r = t % 304;
        int d = r >> 4, j = r & 15;
        w1t[ci*320 + j*20 + d] = g_weights[(ibase + ci)*337 + d*16 + j];
    }
    for (int t = tid; t < 512; t += 256) {
        int ci = t >> 4, j = t & 15;
        b1s[t] = g_weights[(ibase + ci)*337 + 304 + j];
        w2s[t] = g_weights[(ibase + ci)*337 + 320 + j];
    }
    if (tid < 32) b2s[tid] = g_weights[(ibase + tid)*337 + 336];
    if (tid < 96) ctrs[tid] = g_ctr[ibase*3 + tid];
    __syncthreads();

    int n = blockIdx.x * 256 + tid;
    if (n >= N) return;

    const float4* mr = (const float4*)(g_maskf + (size_t)n * 16);
    float4 m0 = mr[0], m1 = mr[1], m2 = mr[2], m3 = mr[3];
    float px = coords[(size_t)n*3], py = coords[(size_t)n*3+1], pz = coords[(size_t)n*3+2];
    size_t ostride = (size_t)N + IC;

    for (int ci = 0; ci < 32; ci++) {
        float dx = px - ctrs[ci*3], dy = py - ctrs[ci*3+1], dz = pz - ctrs[ci*3+2];
        const float* wb = w1t + ci*320;
        float macc = 0.f;
        #pragma unroll
        for (int j = 0; j < 16; j++) {
            const float* wp = wb + j*20;
            float4 a  = *(const float4*)(wp);
            float4 bq = *(const float4*)(wp + 4);
            float4 cq = *(const float4*)(wp + 8);
            float4 dq = *(const float4*)(wp + 12);
            float h = b1s[(ci<<4) + j];
            h = fmaf(m0.x, a.x,  h); h = fmaf(m0.y, a.y,  h); h = fmaf(m0.z, a.z,  h); h = fmaf(m0.w, a.w,  h);
            h = fmaf(m1.x, bq.x, h); h = fmaf(m1.y, bq.y, h); h = fmaf(m1.z, bq.z, h); h = fmaf(m1.w, bq.w, h);
            h = fmaf(m2.x, cq.x, h); h = fmaf(m2.y, cq.y, h); h = fmaf(m2.z, cq.z, h); h = fmaf(m2.w, cq.w, h);
            h = fmaf(m3.x, dq.x, h); h = fmaf(m3.y, dq.y, h); h = fmaf(m3.z, dq.z, h); h = fmaf(m3.w, dq.w, h);
            h = fmaf(dx, wp[16], h); h = fmaf(dy, wp[17], h); h = fmaf(dz, wp[18], h);
            h = fmaxf(h, 0.f);
            macc = fmaf(h, w2s[(ci<<4) + j], macc);
        }
        out[(size_t)(ibase + ci) * ostride + n] = sigmoidf_(macc + b2s[ci]);
    }
}

// ---------------- merge tower layer (16384 pairwise rows) ----------------
__global__ __launch_bounds__(256, 1)
void merge_layer_kernel(const float* __restrict__ xin, float* __restrict__ yout,
                        const float* __restrict__ Wgl,
                        const float* __restrict__ pstats, float* __restrict__ ostats,
                        int layer0) {
    __shared__ float Ws[35*35];
    __shared__ float featS[IC*35];
    __shared__ float smean[35], srstd[35];
    __shared__ float ps[8][70];
    int tid = threadIdx.x;
    for (int t = tid; t < 1225; t += 256) Ws[t] = Wgl[t];
    if (layer0) {
        for (int t = tid; t < IC*35; t += 256) featS[t] = g_feat[t];
    } else if (tid < 35) {
        float s = pstats[tid], q = pstats[64 + tid];
        float m = s / (float)MR;
        float v = q / (float)MR - m*m;
        smean[tid] = m; srstd[tid] = rsqrtf(v + EPSF);
    }
    __syncthreads();

    int row = blockIdx.x * 256 + tid;   // 0..16383 exactly
    float xv[35];
    if (layer0) {
        int i = row >> 7, j = row & 127;
        #pragma unroll
        for (int c = 0; c < 35; c++)
            xv[c] = fmaxf(fabsf(featS[i*35 + c] - featS[j*35 + c]), 1e-6f);
    } else {
        #pragma unroll
        for (int c = 0; c < 35; c++)
            xv[c] = fmaxf((xin[(size_t)row*35 + c] - smean[c]) * srstd[c], 0.f);
    }
    float acc[35];
    #pragma unroll
    for (int c = 0; c < 35; c++) acc[c] = 0.f;
    for (int c = 0; c < 35; c++) {
        float xa = xv[c];
        const float* wr = Ws + c*35;
        #pragma unroll
        for (int c2 = 0; c2 < 35; c2++) acc[c2] = fmaf(xa, wr[c2], acc[c2]);
    }
    #pragma unroll
    for (int c = 0; c < 35; c++) yout[(size_t)row*35 + c] = acc[c];

    int lane = tid & 31, warp = tid >> 5;
    for (int c = 0; c < 35; c++) {
        float s = acc[c]; float q = s * s;
        #pragma unroll
        for (int o = 16; o; o >>= 1) {
            s += __shfl_down_sync(0xffffffffu, s, o);
            q += __shfl_down_sync(0xffffffffu, q, o);
        }
        if (lane == 0) { ps[warp][c] = s; ps[warp][35 + c] = q; }
    }
    __syncthreads();
    if (tid < 70) {
        float t = 0.f;
        #pragma unroll
        for (int w = 0; w < 8; w++) t += ps[w][tid];
        int target = (tid < 35) ? tid : (64 + tid - 35);
        atomicAdd(&ostats[target], t);
    }
}

// ---------------- merge output: bn+relu -> dot Wg_out -> sigmoid -> batch mask ----------------
__global__ __launch_bounds__(256, 1)
void merge_out_kernel(const float* __restrict__ xin,
                      const float* __restrict__ Wgo, const float* __restrict__ bgo,
                      const float* __restrict__ pstats,
                      float* __restrict__ out, int N) {
    __shared__ float wout[35];
    __shared__ float smean[35], srstd[35];
    int tid = threadIdx.x;
    if (tid < 35) {
        wout[tid] = Wgo[tid];
        float s = pstats[tid], q = pstats[64 + tid];
        float m = s / (float)MR;
        float v = q / (float)MR - m*m;
        smean[tid] = m; srstd[tid] = rsqrtf(v + EPSF);
    }
    __syncthreads();
    int row = blockIdx.x * 256 + tid;
    int i = row >> 7, j = row & 127;
    float acc = bgo[0];
    #pragma unroll
    for (int c = 0; c < 35; c++) {
        float x = fmaxf((xin[(size_t)row*35 + c] - smean[c]) * srstd[c], 0.f);
        acc = fmaf(x, wout[c], acc);
    }
    float v = (g_cb[i] != g_cb[j]) ? 0.f : sigmoidf_(acc);
    out[(size_t)i * ((size_t)N + IC) + (size_t)N + j] = v;
}

// ---------------- launch ----------------
extern "C" void kernel_launch(void* const* d_in, const int* in_sizes, int n_in,
                              void* d_out, int out_size) {
    const float* output_feats = (const float*)d_in[0];
    const float* coords       = (const float*)d_in[1];
    const float* heat         = (const float*)d_in[2];
    const int*   batch_idxs   = (const int*)  d_in[3];
    const float* Wm           = (const float*)d_in[4];
    const float* Wm_out       = (const float*)d_in[5];
    const float* bm_out       = (const float*)d_in[6];
    const float* Wk           = (const float*)d_in[7];
    const float* Wk_out       = (const float*)d_in[8];
    const float* bk_out       = (const float*)d_in[9];
    const float* Wg           = (const float*)d_in[10];
    const float* Wg_out       = (const float*)d_in[11];
    const float* bg_out       = (const float*)d_in[12];
    const float* Wwg          = (const float*)d_in[13];
    const float* bwg          = (const float*)d_in[14];
    float* out = (float*)d_out;
    int N = in_sizes[2];

    float *yA, *yB, *mA, *mB, *stats, *mstats;
    cudaGetSymbolAddress((void**)&yA, g_yA);
    cudaGetSymbolAddress((void**)&yB, g_yB);
    cudaGetSymbolAddress((void**)&mA, g_mA);
    cudaGetSymbolAddress((void**)&mB, g_mB);
    cudaGetSymbolAddress((void**)&stats, g_stats);
    cudaGetSymbolAddress((void**)&mstats, g_mstats);

    init_kernel<<<1, 384>>>();
    nms_kernel<<<NB, 1024>>>(heat, coords, batch_idxs, N);

    int tg = (N + 127) / 128;
    tower_layer_kernel<<<tg, 128>>>(output_feats, yA, Wm,        Wk,        nullptr,     stats,       N, 1);
    tower_layer_kernel<<<tg, 128>>>(yA,           yB, Wm + 1024, Wk + 1024, stats,       stats + 128, N, 0);
    tower_layer_kernel<<<tg, 128>>>(yB,           yA, Wm + 2048, Wk + 2048, stats + 128, stats + 256, N, 0);
    feats_kernel<<<tg, 128>>>(yA, Wm_out, bm_out, Wk_out, bk_out, stats + 256, N);

    cand_prep_kernel<<<IC, 352>>>(coords, batch_idxs, Wwg, bwg);

    dim3 mg((N + 255) / 256, 4);
    masks_kernel<<<mg, 256>>>(coords, out, N);

    merge_layer_kernel<<<64, 256>>>(nullptr, mA, Wg,        nullptr,      mstats,       1);
    merge_layer_kernel<<<64, 256>>>(mA,      mB, Wg + 1225, mstats,       mstats + 128, 0);
    merge_layer_kernel<<<64, 256>>>(mB,      mA, Wg + 2450, mstats + 128, mstats + 256, 0);
    merge_out_kernel<<<64, 256>>>(mA, Wg_out, bg_out, mstats + 256, out, N);
}

// round 4
// speedup vs baseline: 1.1639x; 1.1639x over previous
#include <cuda_runtime.h>
#include <math.h>
#include <stdint.h>

#define D32   32
#define OD    16
#define NB    4
#define KK    32
#define R2C   0.09f
#define EPSF  1e-5f
#define NMAX  100000
#define IC    128
#define MR    (IC*IC)

// ---------------- device scratch (no allocations allowed) ----------------
__device__ float g_yA[NMAX*64];
__device__ float g_yB[NMAX*64];
__device__ float g_maskf[NMAX*OD];
__device__ float g_kernf[NMAX*OD];
__device__ float g_stats[3*128];    // towers: [layer*128 + c] = sum, [+64] = sumsq
__device__ float g_mstats[3*128];   // merge tower, 35 cols used
__device__ int   g_topk[IC];
__device__ float g_weights[IC*337];
__device__ float g_feat[IC*35];
__device__ float g_ctr[IC*3];
__device__ int   g_cb[IC];
__device__ float g_mA[MR*35];
__device__ float g_mB[MR*35];
__device__ float g_nmsbuf[NMAX];

__device__ __forceinline__ float sigmoidf_(float x) {
    return 1.0f / (1.0f + __expf(-x));
}

// ---------------- init: zero stat accumulators (graph replays need this) ----------------
__global__ void init_kernel() {
    int t = threadIdx.x;
    if (t < 384) { g_stats[t] = 0.f; g_mstats[t] = 0.f; }
}

// ---------------- greedy top-K NMS, one block per batch, heat staged in L2 ----------------
__global__ __launch_bounds__(1024, 1)
void nms_kernel(const float* __restrict__ heat, const float* __restrict__ coords,
                const int* __restrict__ bidx, int N) {
    int b = blockIdx.x;
    // binary search batch range [s, e)
    int lo = 0, hi = N;
    while (lo < hi) { int m = (lo + hi) >> 1; if (bidx[m] < b) lo = m + 1; else hi = m; }
    int s = lo; hi = N;
    while (lo < hi) { int m = (lo + hi) >> 1; if (bidx[m] <= b) lo = m + 1; else hi = m; }
    int e = lo, nb = e - s;

    float* buf = g_nmsbuf + s;
    for (int t = threadIdx.x; t < nb; t += 1024) buf[t] = heat[s + t];

    __shared__ float rv[32]; __shared__ int ri[32];
    __shared__ float cc[3]; __shared__ int have;
    if (threadIdx.x == 0) have = 0;
    __syncthreads();

    const float NEG = __int_as_float(0xff800000);
    int lane = threadIdx.x & 31, w = threadIdx.x >> 5;

    for (int k = 0; k < KK; k++) {
        int h = have;
        float cx = 0.f, cy = 0.f, cz = 0.f;
        if (h) { cx = cc[0]; cy = cc[1]; cz = cc[2]; }
        float best = NEG; int bi = 0x7fffffff;
        for (int t = threadIdx.x; t < nb; t += 1024) {
            float v = buf[t];
            if (h && v != NEG) {
                int g = s + t;
                float dx = coords[g*3]   - cx;
                float dy = coords[g*3+1] - cy;
                float dz = coords[g*3+2] - cz;
                if (dx*dx + dy*dy + dz*dz < R2C) { v = NEG; buf[t] = NEG; }
            }
            if (v > best) { best = v; bi = t; }   // strict >, ascending t => first max
        }
        #pragma unroll
        for (int o = 16; o; o >>= 1) {
            float ov = __shfl_down_sync(0xffffffffu, best, o);
            int   oi = __shfl_down_sync(0xffffffffu, bi, o);
            if (ov > best || (ov == best && oi < bi)) { best = ov; bi = oi; }
        }
        if (lane == 0) { rv[w] = best; ri[w] = bi; }
        __syncthreads();
        if (w == 0) {
            best = rv[lane]; bi = ri[lane];
            #pragma unroll
            for (int o = 16; o; o >>= 1) {
                float ov = __shfl_down_sync(0xffffffffu, best, o);
                int   oi = __shfl_down_sync(0xffffffffu, bi, o);
                if (ov > best || (ov == best && oi < bi)) { best = ov; bi = oi; }
            }
            if (lane == 0) {
                int chosen = (best == NEG) ? 0 : (s + bi);   // jnp.argmax(all -inf) == 0
                g_topk[b*KK + k] = chosen;
                cc[0] = coords[chosen*3]; cc[1] = coords[chosen*3+1]; cc[2] = coords[chosen*3+2];
                have = 1;
            }
        }
        __syncthreads();
    }
}

// ---------------- one tower layer for BOTH towers (pure GEMM, no stats) ----------------
// y[:, 0:32]  = bnrelu(x_m) @ Wml ;  y[:, 32:64] = bnrelu(x_k) @ Wkl
__global__ __launch_bounds__(256, 1)
void tower_layer_kernel(const float* __restrict__ x, float* __restrict__ y,
                        const float* __restrict__ Wml, const float* __restrict__ Wkl,
                        const float* __restrict__ pstats,
                        int N, int layer0) {
    __shared__ float Ws[32*64];      // [d][ j<32: m, j>=32: k ]
    __shared__ float smean[64], srstd[64];
    for (int t = threadIdx.x; t < 2048; t += 256) {
        int d = t >> 6, j = t & 63;
        Ws[t] = (j < 32) ? Wml[d*32 + j] : Wkl[d*32 + (j - 32)];
    }
    if (!layer0 && threadIdx.x < 64) {
        float s = pstats[threadIdx.x], q = pstats[64 + threadIdx.x];
        float m = s / (float)N;
        float v = q / (float)N - m*m;
        smean[threadIdx.x] = m;
        srstd[threadIdx.x] = rsqrtf(v + EPSF);
    }
    __syncthreads();

    int n = blockIdx.x * 256 + threadIdx.x;
    if (n >= N) return;
    int instr = (layer0 ? 32 : 64);

    #pragma unroll
    for (int half = 0; half < 2; half++) {
        float xv[32];
        float acc[32];
        #pragma unroll
        for (int j = 0; j < 32; j++) acc[j] = 0.f;

        int coff = layer0 ? 0 : half * 32;
        const float4* xr = (const float4*)(x + (size_t)n * instr + coff);
        if (layer0) {
            #pragma unroll
            for (int q = 0; q < 8; q++) {
                float4 v = xr[q]; int d = q*4;
                xv[d] = v.x; xv[d+1] = v.y; xv[d+2] = v.z; xv[d+3] = v.w;
            }
        } else {
            #pragma unroll
            for (int q = 0; q < 8; q++) {
                float4 v = xr[q]; int d = q*4; int c = coff + d;
                xv[d]   = fmaxf((v.x - smean[c])   * srstd[c],   0.f);
                xv[d+1] = fmaxf((v.y - smean[c+1]) * srstd[c+1], 0.f);
                xv[d+2] = fmaxf((v.z - smean[c+2]) * srstd[c+2], 0.f);
                xv[d+3] = fmaxf((v.w - smean[c+3]) * srstd[c+3], 0.f);
            }
        }
        #pragma unroll 4
        for (int d = 0; d < 32; d++) {
            float xa = xv[d];
            const float4* w4 = (const float4*)(Ws + d*64 + half*32);
            #pragma unroll
            for (int q = 0; q < 8; q++) {
                float4 w = w4[q]; int j = q*4;
                acc[j]   = fmaf(xa, w.x, acc[j]);
                acc[j+1] = fmaf(xa, w.y, acc[j+1]);
                acc[j+2] = fmaf(xa, w.z, acc[j+2]);
                acc[j+3] = fmaf(xa, w.w, acc[j+3]);
            }
        }
        float4* yr = (float4*)(y + (size_t)n * 64 + half*32);
        #pragma unroll
        for (int q = 0; q < 8; q++) {
            float4 v; int j = q*4;
            v.x = acc[j]; v.y = acc[j+1]; v.z = acc[j+2]; v.w = acc[j+3];
            yr[q] = v;
        }
    }
}

// ---------------- column stats over y (64 cols): sum + sumsq, no shuffles ----------------
__global__ __launch_bounds__(256, 1)
void colstats_kernel(const float* __restrict__ y, float* __restrict__ ostats, int N) {
    // thread t handles columns (t&15)*4 .. +3 (float4), rows strided by gridDim.x*16
    int tid = threadIdx.x;
    int lane16 = tid & 15;
    float4 s = make_float4(0.f,0.f,0.f,0.f);
    float4 q = make_float4(0.f,0.f,0.f,0.f);
    for (int r = blockIdx.x*16 + (tid >> 4); r < N; r += gridDim.x*16) {
        float4 v = ((const float4*)(y + (size_t)r*64))[lane16];
        s.x += v.x; s.y += v.y; s.z += v.z; s.w += v.w;
        q.x = fmaf(v.x, v.x, q.x); q.y = fmaf(v.y, v.y, q.y);
        q.z = fmaf(v.z, v.z, q.z); q.w = fmaf(v.w, v.w, q.w);
    }
    __shared__ float sm[256][8];
    sm[tid][0] = s.x; sm[tid][1] = s.y; sm[tid][2] = s.z; sm[tid][3] = s.w;
    sm[tid][4] = q.x; sm[tid][5] = q.y; sm[tid][6] = q.z; sm[tid][7] = q.w;
    __syncthreads();
    if (tid < 16) {
        float a0=0,a1=0,a2=0,a3=0,b0=0,b1=0,b2=0,b3=0;
        #pragma unroll
        for (int g = 0; g < 16; g++) {
            float* p = sm[tid + 16*g];
            a0 += p[0]; a1 += p[1]; a2 += p[2]; a3 += p[3];
            b0 += p[4]; b1 += p[5]; b2 += p[6]; b3 += p[7];
        }
        int c = tid*4;
        atomicAdd(&ostats[c],   a0); atomicAdd(&ostats[c+1], a1);
        atomicAdd(&ostats[c+2], a2); atomicAdd(&ostats[c+3], a3);
        atomicAdd(&ostats[64+c],   b0); atomicAdd(&ostats[64+c+1], b1);
        atomicAdd(&ostats[64+c+2], b2); atomicAdd(&ostats[64+c+3], b3);
    }
}

// ---------------- final projection: mask_feats, kernel_feats ----------------
__global__ __launch_bounds__(256, 1)
void feats_kernel(const float* __restrict__ yin,
                  const float* __restrict__ Wmo, const float* __restrict__ bmo,
                  const float* __restrict__ Wko, const float* __restrict__ bko,
                  const float* __restrict__ pstats, int N) {
    __shared__ float Wos[32*32];   // [d][ j<16: m-tower, j>=16: k-tower ]
    __shared__ float bs[32];
    __shared__ float smean[64], srstd[64];
    for (int t = threadIdx.x; t < 1024; t += 256) {
        int d = t >> 5, j = t & 31;
        Wos[t] = (j < 16) ? Wmo[d*16 + j] : Wko[d*16 + (j - 16)];
    }
    if (threadIdx.x < 32) bs[threadIdx.x] = (threadIdx.x < 16) ? bmo[threadIdx.x] : bko[threadIdx.x - 16];
    if (threadIdx.x < 64) {
        float s = pstats[threadIdx.x], q = pstats[64 + threadIdx.x];
        float m = s / (float)N;
        float v = q / (float)N - m*m;
        smean[threadIdx.x] = m; srstd[threadIdx.x] = rsqrtf(v + EPSF);
    }
    __syncthreads();
    int n = blockIdx.x * 256 + threadIdx.x;
    if (n >= N) return;

    #pragma unroll
    for (int half = 0; half < 2; half++) {
        float xv[32];
        const float4* xr = (const float4*)(yin + (size_t)n * 64 + half*32);
        #pragma unroll
        for (int q = 0; q < 8; q++) {
            float4 v = xr[q]; int d = q*4; int c = half*32 + d;
            xv[d]   = fmaxf((v.x - smean[c])   * srstd[c],   0.f);
            xv[d+1] = fmaxf((v.y - smean[c+1]) * srstd[c+1], 0.f);
            xv[d+2] = fmaxf((v.z - smean[c+2]) * srstd[c+2], 0.f);
            xv[d+3] = fmaxf((v.w - smean[c+3]) * srstd[c+3], 0.f);
        }
        float acc[16];
        #pragma unroll
        for (int j = 0; j < 16; j++) acc[j] = 0.f;
        #pragma unroll 4
        for (int d = 0; d < 32; d++) {
            float xa = xv[d];
            const float4* w4 = (const float4*)(Wos + d*32 + half*16);
            #pragma unroll
            for (int q = 0; q < 4; q++) {
                float4 w = w4[q]; int j = q*4;
                acc[j]   = fmaf(xa, w.x, acc[j]);
                acc[j+1] = fmaf(xa, w.y, acc[j+1]);
                acc[j+2] = fmaf(xa, w.z, acc[j+2]);
                acc[j+3] = fmaf(xa, w.w, acc[j+3]);
            }
        }
        float* dst = half ? (g_kernf + (size_t)n * 16) : (g_maskf + (size_t)n * 16);
        float4* o4 = (float4*)dst;
        #pragma unroll
        for (int q = 0; q < 4; q++) {
            float4 v; int j = q*4; int bj = half*16 + j;
            v.x = acc[j] + bs[bj]; v.y = acc[j+1] + bs[bj+1];
            v.z = acc[j+2] + bs[bj+2]; v.w = acc[j+3] + bs[bj+3];
            o4[q] = v;
        }
    }
}

// ---------------- candidate gather + weight generator (128 blocks) ----------------
__global__ void cand_prep_kernel(const float* __restrict__ coords, const int* __restrict__ bidx,
                                 const float* __restrict__ Wwg, const float* __restrict__ bwg) {
    int i = blockIdx.x;
    int tid = threadIdx.x;
    __shared__ float ck[16];
    __shared__ int sidx;
    if (tid == 0) sidx = g_topk[i];
    __syncthreads();
    int idx = sidx;
    if (tid < 16) {
        float v = g_kernf[(size_t)idx*16 + tid];
        ck[tid] = v;
        g_feat[i*35 + tid] = v;
    } else if (tid < 32) {
        g_feat[i*35 + tid] = g_maskf[(size_t)idx*16 + (tid - 16)];
    } else if (tid < 35) {
        float c = coords[(size_t)idx*3 + (tid - 32)];
        g_feat[i*35 + tid] = c;
        g_ctr[i*3 + (tid - 32)] = c;
    } else if (tid == 35) {
        g_cb[i] = bidx[idx];
    }
    __syncthreads();
    if (tid < 337) {
        float w = bwg[tid];
        #pragma unroll
        for (int d = 0; d < 16; d++) w = fmaf(ck[d], Wwg[d*337 + tid], w);
        g_weights[i*337 + tid] = w;
    }
}

// ---------------- dynamic mask head: 4 points per thread ----------------
__global__ __launch_bounds__(128, 1)
void masks_kernel(const float* __restrict__ coords, float* __restrict__ out, int N) {
    // 32 candidates per block (blockIdx.y), 512 points per block (blockIdx.x), 4 pts/thread
    __shared__ float w1t[32*320];    // [ci][j][d0..18], padded to 20 (80B)
    __shared__ float b1s[512];
    __shared__ float w2s[512];
    __shared__ float b2s[32];
    __shared__ float ctrs[96];
    int ibase = blockIdx.y * 32;
    int tid = threadIdx.x;

    for (int t = tid; t < 32*304; t += 128) {
        int ci = t / 304, r = t % 304;
        int d = r >> 4, j = r & 15;
        w1t[ci*320 + j*20 + d] = g_weights[(ibase + ci)*337 + d*16 + j];
    }
    for (int t = tid; t < 512; t += 128) {
        int ci = t >> 4, j = t & 15;
        b1s[t] = g_weights[(ibase + ci)*337 + 304 + j];
        w2s[t] = g_weights[(ibase + ci)*337 + 320 + j];
    }
    if (tid < 32) b2s[tid] = g_weights[(ibase + tid)*337 + 336];
    if (tid < 96) ctrs[tid] = g_ctr[ibase*3 + tid];
    __syncthreads();

    int n0 = blockIdx.x * 512 + tid;
    float4 m0[4], m1[4], m2[4], m3[4];
    float px[4], py[4], pz[4];
    bool val[4];
    #pragma unroll
    for (int k = 0; k < 4; k++) {
        int n = n0 + k*128;
        val[k] = (n < N);
        int ns = val[k] ? n : (N - 1);
        const float4* mr = (const float4*)(g_maskf + (size_t)ns * 16);
        m0[k] = mr[0]; m1[k] = mr[1]; m2[k] = mr[2]; m3[k] = mr[3];
        px[k] = coords[(size_t)ns*3]; py[k] = coords[(size_t)ns*3+1]; pz[k] = coords[(size_t)ns*3+2];
    }
    size_t ostride = (size_t)N + IC;

    for (int ci = 0; ci < 32; ci++) {
        float cx = ctrs[ci*3], cy = ctrs[ci*3+1], cz = ctrs[ci*3+2];
        float dx[4], dy[4], dz[4], macc[4];
        #pragma unroll
        for (int k = 0; k < 4; k++) {
            dx[k] = px[k] - cx; dy[k] = py[k] - cy; dz[k] = pz[k] - cz;
            macc[k] = 0.f;
        }
        const float* wb = w1t + ci*320;
        #pragma unroll 4
        for (int j = 0; j < 16; j++) {
            const float* wp = wb + j*20;
            float4 a  = *(const float4*)(wp);
            float4 bq = *(const float4*)(wp + 4);
            float4 cq = *(const float4*)(wp + 8);
            float4 dq = *(const float4*)(wp + 12);
            float w16 = wp[16], w17 = wp[17], w18 = wp[18];
            float b1 = b1s[(ci<<4) + j], w2 = w2s[(ci<<4) + j];
            #pragma unroll
            for (int k = 0; k < 4; k++) {
                float h = b1;
                h = fmaf(m0[k].x, a.x,  h); h = fmaf(m0[k].y, a.y,  h);
                h = fmaf(m0[k].z, a.z,  h); h = fmaf(m0[k].w, a.w,  h);
                h = fmaf(m1[k].x, bq.x, h); h = fmaf(m1[k].y, bq.y, h);
                h = fmaf(m1[k].z, bq.z, h); h = fmaf(m1[k].w, bq.w, h);
                h = fmaf(m2[k].x, cq.x, h); h = fmaf(m2[k].y, cq.y, h);
                h = fmaf(m2[k].z, cq.z, h); h = fmaf(m2[k].w, cq.w, h);
                h = fmaf(m3[k].x, dq.x, h); h = fmaf(m3[k].y, dq.y, h);
                h = fmaf(m3[k].z, dq.z, h); h = fmaf(m3[k].w, dq.w, h);
                h = fmaf(dx[k], w16, h); h = fmaf(dy[k], w17, h); h = fmaf(dz[k], w18, h);
                h = fmaxf(h, 0.f);
                macc[k] = fmaf(h, w2, macc[k]);
            }
        }
        float b2v = b2s[ci];
        float* orow = out + (size_t)(ibase + ci) * ostride;
        #pragma unroll
        for (int k = 0; k < 4; k++)
            if (val[k]) orow[n0 + k*128] = sigmoidf_(macc[k] + b2v);
    }
}

// ---------------- merge tower layer (16384 pairwise rows) ----------------
__global__ __launch_bounds__(256, 1)
void merge_layer_kernel(const float* __restrict__ xin, float* __restrict__ yout,
                        const float* __restrict__ Wgl,
                        const float* __restrict__ pstats, float* __restrict__ ostats,
                        int layer0) {
    __shared__ float Ws[35*35];
    __shared__ float featS[IC*35];
    __shared__ float smean[35], srstd[35];
    __shared__ float ps[8][70];
    int tid = threadIdx.x;
    for (int t = tid; t < 1225; t += 256) Ws[t] = Wgl[t];
    if (layer0) {
        for (int t = tid; t < IC*35; t += 256) featS[t] = g_feat[t];
    } else if (tid < 35) {
        float s = pstats[tid], q = pstats[64 + tid];
        float m = s / (float)MR;
        float v = q / (float)MR - m*m;
        smean[tid] = m; srstd[tid] = rsqrtf(v + EPSF);
    }
    __syncthreads();

    int row = blockIdx.x * 256 + tid;   // 0..16383 exactly
    float xv[35];
    if (layer0) {
        int i = row >> 7, j = row & 127;
        #pragma unroll
        for (int c = 0; c < 35; c++)
            xv[c] = fmaxf(fabsf(featS[i*35 + c] - featS[j*35 + c]), 1e-6f);
    } else {
        #pragma unroll
        for (int c = 0; c < 35; c++)
            xv[c] = fmaxf((xin[(size_t)row*35 + c] - smean[c]) * srstd[c], 0.f);
    }
    float acc[35];
    #pragma unroll
    for (int c = 0; c < 35; c++) acc[c] = 0.f;
    for (int c = 0; c < 35; c++) {
        float xa = xv[c];
        const float* wr = Ws + c*35;
        #pragma unroll
        for (int c2 = 0; c2 < 35; c2++) acc[c2] = fmaf(xa, wr[c2], acc[c2]);
    }
    #pragma unroll
    for (int c = 0; c < 35; c++) yout[(size_t)row*35 + c] = acc[c];

    int lane = tid & 31, warp = tid >> 5;
    for (int c = 0; c < 35; c++) {
        float s = acc[c]; float q = s * s;
        #pragma unroll
        for (int o = 16; o; o >>= 1) {
            s += __shfl_down_sync(0xffffffffu, s, o);
            q += __shfl_down_sync(0xffffffffu, q, o);
        }
        if (lane == 0) { ps[warp][c] = s; ps[warp][35 + c] = q; }
    }
    __syncthreads();
    if (tid < 70) {
        float t = 0.f;
        #pragma unroll
        for (int w = 0; w < 8; w++) t += ps[w][tid];
        int target = (tid < 35) ? tid : (64 + tid - 35);
        atomicAdd(&ostats[target], t);
    }
}

// ---------------- merge output: bn+relu -> dot Wg_out -> sigmoid -> batch mask ----------------
__global__ __launch_bounds__(256, 1)
void merge_out_kernel(const float* __restrict__ xin,
                      const float* __restrict__ Wgo, const float* __restrict__ bgo,
                      const float* __restrict__ pstats,
                      float* __restrict__ out, int N) {
    __shared__ float wout[35];
    __shared__ float smean[35], srstd[35];
    int tid = threadIdx.x;
    if (tid < 35) {
        wout[tid] = Wgo[tid];
        float s = pstats[tid], q = pstats[64 + tid];
        float m = s / (float)MR;
        float v = q / (float)MR - m*m;
        smean[tid] = m; srstd[tid] = rsqrtf(v + EPSF);
    }
    __syncthreads();
    int row = blockIdx.x * 256 + tid;
    int i = row >> 7, j = row & 127;
    float acc = bgo[0];
    #pragma unroll
    for (int c = 0; c < 35; c++) {
        float x = fmaxf((xin[(size_t)row*35 + c] - smean[c]) * srstd[c], 0.f);
        acc = fmaf(x, wout[c], acc);
    }
    float v = (g_cb[i] != g_cb[j]) ? 0.f : sigmoidf_(acc);
    out[(size_t)i * ((size_t)N + IC) + (size_t)N + j] = v;
}

// ---------------- launch ----------------
extern "C" void kernel_launch(void* const* d_in, const int* in_sizes, int n_in,
                              void* d_out, int out_size) {
    const float* output_feats = (const float*)d_in[0];
    const float* coords       = (const float*)d_in[1];
    const float* heat         = (const float*)d_in[2];
    const int*   batch_idxs   = (const int*)  d_in[3];
    const float* Wm           = (const float*)d_in[4];
    const float* Wm_out       = (const float*)d_in[5];
    const float* bm_out       = (const float*)d_in[6];
    const float* Wk           = (const float*)d_in[7];
    const float* Wk_out       = (const float*)d_in[8];
    const float* bk_out       = (const float*)d_in[9];
    const float* Wg           = (const float*)d_in[10];
    const float* Wg_out       = (const float*)d_in[11];
    const float* bg_out       = (const float*)d_in[12];
    const float* Wwg          = (const float*)d_in[13];
    const float* bwg          = (const float*)d_in[14];
    float* out = (float*)d_out;
    int N = in_sizes[2];

    float *yA, *yB, *mA, *mB, *stats, *mstats;
    cudaGetSymbolAddress((void**)&yA, g_yA);
    cudaGetSymbolAddress((void**)&yB, g_yB);
    cudaGetSymbolAddress((void**)&mA, g_mA);
    cudaGetSymbolAddress((void**)&mB, g_mB);
    cudaGetSymbolAddress((void**)&stats, g_stats);
    cudaGetSymbolAddress((void**)&mstats, g_mstats);

    init_kernel<<<1, 384>>>();
    nms_kernel<<<NB, 1024>>>(heat, coords, batch_idxs, N);

    int tg = (N + 255) / 256;
    tower_layer_kernel<<<tg, 256>>>(output_feats, yA, Wm,        Wk,        nullptr,     N, 1);
    colstats_kernel<<<128, 256>>>(yA, stats, N);
    tower_layer_kernel<<<tg, 256>>>(yA,           yB, Wm + 1024, Wk + 1024, stats,       N, 0);
    colstats_kernel<<<128, 256>>>(yB, stats + 128, N);
    tower_layer_kernel<<<tg, 256>>>(yB,           yA, Wm + 2048, Wk + 2048, stats + 128, N, 0);
    colstats_kernel<<<128, 256>>>(yA, stats + 256, N);
    feats_kernel<<<tg, 256>>>(yA, Wm_out, bm_out, Wk_out, bk_out, stats + 256, N);

    cand_prep_kernel<<<IC, 352>>>(coords, batch_idxs, Wwg, bwg);

    dim3 mg((N + 511) / 512, 4);
    masks_kernel<<<mg, 128>>>(coords, out, N);

    merge_layer_kernel<<<64, 256>>>(nullptr, mA, Wg,        nullptr,      mstats,       1);
    merge_layer_kernel<<<64, 256>>>(mA,      mB, Wg + 1225, mstats,       mstats + 128, 0);
    merge_layer_kernel<<<64, 256>>>(mB,      mA, Wg + 2450, mstats + 128, mstats + 256, 0);
    merge_out_kernel<<<64, 256>>>(mA, Wg_out, bg_out, mstats + 256, out, N);
}

// round 5
// speedup vs baseline: 1.2029x; 1.0335x over previous
#include <cuda_runtime.h>
#include <math.h>
#include <stdint.h>

#define D32   32
#define OD    16
#define NB    4
#define KK    32
#define R2C   0.09f
#define EPSF  1e-5f
#define NMAX  100000
#define IC    128
#define MR    (IC*IC)

typedef unsigned long long u64;

// ---------------- device scratch (no allocations allowed) ----------------
__device__ float g_yA[NMAX*64];
__device__ float g_yB[NMAX*64];
__device__ float g_maskf[NMAX*OD];
__device__ float g_kernf[NMAX*OD];
__device__ float g_stats[3*128];    // towers: [layer*128 + c] = sum, [+64] = sumsq
__device__ float g_mstats[3*128];   // merge tower, 35 cols used
__device__ int   g_topk[IC];
__device__ float g_feat[IC*35];
__device__ float g_ctr[IC*3];
__device__ int   g_cb[IC];
__device__ float g_mA[MR*35];
__device__ float g_mB[MR*35];
__device__ float g_nmsbuf[NMAX];
// candidate-pair interleaved mask-head weights:
// g_w1aug2[pair][j][d*2 + (i&1)], pair=i>>1, d=0..19 (d==19 is folded bias)
__device__ float g_w1aug2[64*16*40];
__device__ float g_w2p[64*16*2];
__device__ float g_b2p[64*2];

__device__ __forceinline__ float sigmoidf_(float x) {
    return 1.0f / (1.0f + __expf(-x));
}
__device__ __forceinline__ u64 pack2(float lo, float hi) {
    u64 r; asm("mov.b64 %0, {%1, %2};" : "=l"(r) : "f"(lo), "f"(hi)); return r;
}
__device__ __forceinline__ u64 dup2(float x) { return pack2(x, x); }
__device__ __forceinline__ void unpack2(u64 v, float &lo, float &hi) {
    asm("mov.b64 {%0, %1}, %2;" : "=f"(lo), "=f"(hi) : "l"(v));
}
__device__ __forceinline__ u64 ffma2(u64 a, u64 b, u64 c) {
    u64 d; asm("fma.rn.f32x2 %0, %1, %2, %3;" : "=l"(d) : "l"(a), "l"(b), "l"(c)); return d;
}

// ---------------- init: zero stat accumulators (graph replays need this) ----------------
__global__ void init_kernel() {
    int t = threadIdx.x;
    if (t < 384) { g_stats[t] = 0.f; g_mstats[t] = 0.f; }
}

// ---------------- greedy top-K NMS, one block per batch, heat staged in L2 ----------------
__global__ __launch_bounds__(1024, 1)
void nms_kernel(const float* __restrict__ heat, const float* __restrict__ coords,
                const int* __restrict__ bidx, int N) {
    int b = blockIdx.x;
    int lo = 0, hi = N;
    while (lo < hi) { int m = (lo + hi) >> 1; if (bidx[m] < b) lo = m + 1; else hi = m; }
    int s = lo; hi = N;
    while (lo < hi) { int m = (lo + hi) >> 1; if (bidx[m] <= b) lo = m + 1; else hi = m; }
    int e = lo, nb = e - s;

    float* buf = g_nmsbuf + s;
    for (int t = threadIdx.x; t < nb; t += 1024) buf[t] = heat[s + t];

    __shared__ float rv[32]; __shared__ int ri[32];
    __shared__ float cc[3]; __shared__ int have;
    if (threadIdx.x == 0) have = 0;
    __syncthreads();

    const float NEG = __int_as_float(0xff800000);
    int lane = threadIdx.x & 31, w = threadIdx.x >> 5;

    for (int k = 0; k < KK; k++) {
        int h = have;
        float cx = 0.f, cy = 0.f, cz = 0.f;
        if (h) { cx = cc[0]; cy = cc[1]; cz = cc[2]; }
        float best = NEG; int bi = 0x7fffffff;
        for (int t = threadIdx.x; t < nb; t += 1024) {
            float v = buf[t];
            if (h && v != NEG) {
                int g = s + t;
                float dx = coords[g*3]   - cx;
                float dy = coords[g*3+1] - cy;
                float dz = coords[g*3+2] - cz;
                if (dx*dx + dy*dy + dz*dz < R2C) { v = NEG; buf[t] = NEG; }
            }
            if (v > best) { best = v; bi = t; }
        }
        #pragma unroll
        for (int o = 16; o; o >>= 1) {
            float ov = __shfl_down_sync(0xffffffffu, best, o);
            int   oi = __shfl_down_sync(0xffffffffu, bi, o);
            if (ov > best || (ov == best && oi < bi)) { best = ov; bi = oi; }
        }
        if (lane == 0) { rv[w] = best; ri[w] = bi; }
        __syncthreads();
        if (w == 0) {
            best = rv[lane]; bi = ri[lane];
            #pragma unroll
            for (int o = 16; o; o >>= 1) {
                float ov = __shfl_down_sync(0xffffffffu, best, o);
                int   oi = __shfl_down_sync(0xffffffffu, bi, o);
                if (ov > best || (ov == best && oi < bi)) { best = ov; bi = oi; }
            }
            if (lane == 0) {
                int chosen = (best == NEG) ? 0 : (s + bi);
                g_topk[b*KK + k] = chosen;
                cc[0] = coords[chosen*3]; cc[1] = coords[chosen*3+1]; cc[2] = coords[chosen*3+2];
                have = 1;
            }
        }
        __syncthreads();
    }
}

// ---------------- one tower layer for BOTH towers (pure GEMM, FFMA2) ----------------
__global__ __launch_bounds__(256, 1)
void tower_layer_kernel(const float* __restrict__ x, float* __restrict__ y,
                        const float* __restrict__ Wml, const float* __restrict__ Wkl,
                        const float* __restrict__ pstats,
                        int N, int layer0) {
    __shared__ float Ws[32*64];      // [d][ j<32: m, j>=32: k ]
    __shared__ float smean[64], srstd[64];
    for (int t = threadIdx.x; t < 2048; t += 256) {
        int d = t >> 6, j = t & 63;
        Ws[t] = (j < 32) ? Wml[d*32 + j] : Wkl[d*32 + (j - 32)];
    }
    if (!layer0 && threadIdx.x < 64) {
        float s = pstats[threadIdx.x], q = pstats[64 + threadIdx.x];
        float m = s / (float)N;
        float v = q / (float)N - m*m;
        smean[threadIdx.x] = m;
        srstd[threadIdx.x] = rsqrtf(v + EPSF);
    }
    __syncthreads();

    int n = blockIdx.x * 256 + threadIdx.x;
    if (n >= N) return;
    int instr = (layer0 ? 32 : 64);

    #pragma unroll
    for (int half = 0; half < 2; half++) {
        float xv[32];
        u64 acc[16];
        #pragma unroll
        for (int j = 0; j < 16; j++) acc[j] = 0ull;

        int coff = layer0 ? 0 : half * 32;
        const float4* xr = (const float4*)(x + (size_t)n * instr + coff);
        if (layer0) {
            #pragma unroll
            for (int q = 0; q < 8; q++) {
                float4 v = xr[q]; int d = q*4;
                xv[d] = v.x; xv[d+1] = v.y; xv[d+2] = v.z; xv[d+3] = v.w;
            }
        } else {
            #pragma unroll
            for (int q = 0; q < 8; q++) {
                float4 v = xr[q]; int d = q*4; int c = coff + d;
                xv[d]   = fmaxf((v.x - smean[c])   * srstd[c],   0.f);
                xv[d+1] = fmaxf((v.y - smean[c+1]) * srstd[c+1], 0.f);
                xv[d+2] = fmaxf((v.z - smean[c+2]) * srstd[c+2], 0.f);
                xv[d+3] = fmaxf((v.w - smean[c+3]) * srstd[c+3], 0.f);
            }
        }
        #pragma unroll 4
        for (int d = 0; d < 32; d++) {
            u64 xd = dup2(xv[d]);
            const u64* wr = (const u64*)(Ws + d*64 + half*32);
            #pragma unroll
            for (int q = 0; q < 16; q++) acc[q] = ffma2(xd, wr[q], acc[q]);
        }
        ulonglong2* yr = (ulonglong2*)(y + (size_t)n * 64 + half*32);
        #pragma unroll
        for (int q = 0; q < 8; q++) yr[q] = make_ulonglong2(acc[2*q], acc[2*q+1]);
    }
}

// ---------------- column stats over y (64 cols): sum + sumsq ----------------
__global__ __launch_bounds__(256, 1)
void colstats_kernel(const float* __restrict__ y, float* __restrict__ ostats, int N) {
    int tid = threadIdx.x;
    int lane16 = tid & 15;
    float4 s = make_float4(0.f,0.f,0.f,0.f);
    float4 q = make_float4(0.f,0.f,0.f,0.f);
    #pragma unroll 4
    for (int r = blockIdx.x*16 + (tid >> 4); r < N; r += gridDim.x*16) {
        float4 v = ((const float4*)(y + (size_t)r*64))[lane16];
        s.x += v.x; s.y += v.y; s.z += v.z; s.w += v.w;
        q.x = fmaf(v.x, v.x, q.x); q.y = fmaf(v.y, v.y, q.y);
        q.z = fmaf(v.z, v.z, q.z); q.w = fmaf(v.w, v.w, q.w);
    }
    __shared__ float sm[256][8];
    sm[tid][0] = s.x; sm[tid][1] = s.y; sm[tid][2] = s.z; sm[tid][3] = s.w;
    sm[tid][4] = q.x; sm[tid][5] = q.y; sm[tid][6] = q.z; sm[tid][7] = q.w;
    __syncthreads();
    if (tid < 16) {
        float a0=0,a1=0,a2=0,a3=0,b0=0,b1=0,b2=0,b3=0;
        #pragma unroll
        for (int g = 0; g < 16; g++) {
            float* p = sm[tid + 16*g];
            a0 += p[0]; a1 += p[1]; a2 += p[2]; a3 += p[3];
            b0 += p[4]; b1 += p[5]; b2 += p[6]; b3 += p[7];
        }
        int c = tid*4;
        atomicAdd(&ostats[c],   a0); atomicAdd(&ostats[c+1], a1);
        atomicAdd(&ostats[c+2], a2); atomicAdd(&ostats[c+3], a3);
        atomicAdd(&ostats[64+c],   b0); atomicAdd(&ostats[64+c+1], b1);
        atomicAdd(&ostats[64+c+2], b2); atomicAdd(&ostats[64+c+3], b3);
    }
}

// ---------------- final projection: mask_feats, kernel_feats ----------------
__global__ __launch_bounds__(256, 1)
void feats_kernel(const float* __restrict__ yin,
                  const float* __restrict__ Wmo, const float* __restrict__ bmo,
                  const float* __restrict__ Wko, const float* __restrict__ bko,
                  const float* __restrict__ pstats, int N) {
    __shared__ float Wos[32*32];   // [d][ j<16: m-tower, j>=16: k-tower ]
    __shared__ float bs[32];
    __shared__ float smean[64], srstd[64];
    for (int t = threadIdx.x; t < 1024; t += 256) {
        int d = t >> 5, j = t & 31;
        Wos[t] = (j < 16) ? Wmo[d*16 + j] : Wko[d*16 + (j - 16)];
    }
    if (threadIdx.x < 32) bs[threadIdx.x] = (threadIdx.x < 16) ? bmo[threadIdx.x] : bko[threadIdx.x - 16];
    if (threadIdx.x < 64) {
        float s = pstats[threadIdx.x], q = pstats[64 + threadIdx.x];
        float m = s / (float)N;
        float v = q / (float)N - m*m;
        smean[threadIdx.x] = m; srstd[threadIdx.x] = rsqrtf(v + EPSF);
    }
    __syncthreads();
    int n = blockIdx.x * 256 + threadIdx.x;
    if (n >= N) return;

    #pragma unroll
    for (int half = 0; half < 2; half++) {
        float xv[32];
        const float4* xr = (const float4*)(yin + (size_t)n * 64 + half*32);
        #pragma unroll
        for (int q = 0; q < 8; q++) {
            float4 v = xr[q]; int d = q*4; int c = half*32 + d;
            xv[d]   = fmaxf((v.x - smean[c])   * srstd[c],   0.f);
            xv[d+1] = fmaxf((v.y - smean[c+1]) * srstd[c+1], 0.f);
            xv[d+2] = fmaxf((v.z - smean[c+2]) * srstd[c+2], 0.f);
            xv[d+3] = fmaxf((v.w - smean[c+3]) * srstd[c+3], 0.f);
        }
        u64 acc[8];
        #pragma unroll
        for (int j = 0; j < 8; j++) acc[j] = 0ull;
        #pragma unroll 4
        for (int d = 0; d < 32; d++) {
            u64 xd = dup2(xv[d]);
            const u64* wr = (const u64*)(Wos + d*32 + half*16);
            #pragma unroll
            for (int q = 0; q < 8; q++) acc[q] = ffma2(xd, wr[q], acc[q]);
        }
        float* dst = half ? (g_kernf + (size_t)n * 16) : (g_maskf + (size_t)n * 16);
        #pragma unroll
        for (int q = 0; q < 8; q++) {
            float lo, hi; unpack2(acc[q], lo, hi);
            int j = q*2; int bj = half*16 + j;
            dst[j] = lo + bs[bj]; dst[j+1] = hi + bs[bj+1];
        }
    }
}

// ---------------- candidate gather + weight generator + aug-weight build ----------------
__global__ void cand_prep_kernel(const float* __restrict__ coords, const int* __restrict__ bidx,
                                 const float* __restrict__ Wwg, const float* __restrict__ bwg) {
    int i = blockIdx.x;
    int tid = threadIdx.x;
    __shared__ float ck[16];
    __shared__ float ws[337];
    __shared__ float cc[3];
    __shared__ int sidx;
    if (tid == 0) sidx = g_topk[i];
    __syncthreads();
    int idx = sidx;
    if (tid < 16) {
        float v = g_kernf[(size_t)idx*16 + tid];
        ck[tid] = v;
        g_feat[i*35 + tid] = v;
    } else if (tid < 32) {
        g_feat[i*35 + tid] = g_maskf[(size_t)idx*16 + (tid - 16)];
    } else if (tid < 35) {
        float c = coords[(size_t)idx*3 + (tid - 32)];
        g_feat[i*35 + tid] = c;
        g_ctr[i*3 + (tid - 32)] = c;
        cc[tid - 32] = c;
    } else if (tid == 35) {
        g_cb[i] = bidx[idx];
    }
    __syncthreads();
    if (tid < 337) {
        float w = bwg[tid];
        #pragma unroll
        for (int d = 0; d < 16; d++) w = fmaf(ck[d], Wwg[d*337 + tid], w);
        ws[tid] = w;
    }
    __syncthreads();
    // build interleaved aug weights: pair = i>>1, half = i&1
    int pair = i >> 1, hf = i & 1;
    float cx = cc[0], cy = cc[1], cz = cc[2];
    for (int t = tid; t < 320; t += blockDim.x) {
        int j = t / 20, d = t % 20;
        float v;
        if (d < 16)      v = ws[d*16 + j];
        else if (d < 19) v = ws[(16 + (d-16))*16 + j];
        else             v = ws[304 + j] - cx*ws[256 + j] - cy*ws[272 + j] - cz*ws[288 + j];
        g_w1aug2[pair*640 + j*40 + d*2 + hf] = v;
    }
    if (tid < 16) g_w2p[pair*32 + tid*2 + hf] = ws[320 + tid];
    if (tid == 16) g_b2p[pair*2 + hf] = ws[336];
}

// ---------------- dynamic mask head: FFMA2 over candidate pairs, 2 pts/thread ----------------
__global__ __launch_bounds__(128, 1)
void masks_kernel(const float* __restrict__ coords, float* __restrict__ out, int N) {
    __shared__ float w1t[16*16*40];   // [cp][j][d*2+half]  (40960 B)
    __shared__ float w2s[16*16*2];    // [cp][j] pair
    __shared__ float b2s[16*2];       // [cp] pair
    int tid = threadIdx.x;
    int pbase = blockIdx.y * 16;      // candidate-pair base

    {
        const float4* src = (const float4*)(g_w1aug2 + pbase*640);
        float4* dst = (float4*)w1t;
        for (int t = tid; t < 2560; t += 128) dst[t] = src[t];
        for (int t = tid; t < 512; t += 128) w2s[t] = g_w2p[pbase*32 + t];
        if (tid < 32) b2s[tid] = g_b2p[pbase*2 + tid];
    }
    __syncthreads();

    int n0 = blockIdx.x * 256 + tid;
    int n1 = n0 + 128;
    bool v0 = (n0 < N), v1 = (n1 < N);
    int s0 = v0 ? n0 : (N - 1);
    int s1 = v1 ? n1 : (N - 1);

    // duplicated point features: 16 maskf + 3 coords
    u64 x0[19], x1[19];
    {
        const float4* mr = (const float4*)(g_maskf + (size_t)s0 * 16);
        #pragma unroll
        for (int q = 0; q < 4; q++) {
            float4 m = mr[q];
            x0[q*4]   = dup2(m.x); x0[q*4+1] = dup2(m.y);
            x0[q*4+2] = dup2(m.z); x0[q*4+3] = dup2(m.w);
        }
        x0[16] = dup2(coords[(size_t)s0*3]);
        x0[17] = dup2(coords[(size_t)s0*3+1]);
        x0[18] = dup2(coords[(size_t)s0*3+2]);
    }
    {
        const float4* mr = (const float4*)(g_maskf + (size_t)s1 * 16);
        #pragma unroll
        for (int q = 0; q < 4; q++) {
            float4 m = mr[q];
            x1[q*4]   = dup2(m.x); x1[q*4+1] = dup2(m.y);
            x1[q*4+2] = dup2(m.z); x1[q*4+3] = dup2(m.w);
        }
        x1[16] = dup2(coords[(size_t)s1*3]);
        x1[17] = dup2(coords[(size_t)s1*3+1]);
        x1[18] = dup2(coords[(size_t)s1*3+2]);
    }

    size_t ostride = (size_t)N + IC;
    const u64* w2q = (const u64*)w2s;

    for (int cp = 0; cp < 16; cp++) {
        u64 macc0 = 0ull, macc1 = 0ull;
        const float* wb = w1t + cp*640;
        #pragma unroll 4
        for (int j = 0; j < 16; j++) {
            const u64* wq = (const u64*)(wb + j*40);
            u64 h0 = wq[19];
            u64 h1 = h0;
            #pragma unroll
            for (int d = 0; d < 19; d++) {
                u64 wd = wq[d];
                h0 = ffma2(x0[d], wd, h0);
                h1 = ffma2(x1[d], wd, h1);
            }
            u64 w2v = w2q[cp*16 + j];
            float a, b;
            unpack2(h0, a, b);
            h0 = pack2(fmaxf(a, 0.f), fmaxf(b, 0.f));
            macc0 = ffma2(h0, w2v, macc0);
            unpack2(h1, a, b);
            h1 = pack2(fmaxf(a, 0.f), fmaxf(b, 0.f));
            macc1 = ffma2(h1, w2v, macc1);
        }
        float ba = b2s[cp*2], bb = b2s[cp*2+1];
        int ci0 = (pbase + cp) * 2;      // global candidate index
        float* row0 = out + (size_t)ci0 * ostride;
        float* row1 = out + (size_t)(ci0 + 1) * ostride;
        float a, b;
        unpack2(macc0, a, b);
        if (v0) { row0[n0] = sigmoidf_(a + ba); row1[n0] = sigmoidf_(b + bb); }
        unpack2(macc1, a, b);
        if (v1) { row0[n1] = sigmoidf_(a + ba); row1[n1] = sigmoidf_(b + bb); }
    }
}

// ---------------- merge tower layer (16384 pairwise rows) ----------------
__global__ __launch_bounds__(256, 1)
void merge_layer_kernel(const float* __restrict__ xin, float* __restrict__ yout,
                        const float* __restrict__ Wgl,
                        const float* __restrict__ pstats, float* __restrict__ ostats,
                        int layer0) {
    __shared__ float Ws[35*35];
    __shared__ float featS[IC*35];
    __shared__ float smean[35], srstd[35];
    __shared__ float ps[8][70];
    int tid = threadIdx.x;
    for (int t = tid; t < 1225; t += 256) Ws[t] = Wgl[t];
    if (layer0) {
        for (int t = tid; t < IC*35; t += 256) featS[t] = g_feat[t];
    } else if (tid < 35) {
        float s = pstats[tid], q = pstats[64 + tid];
        float m = s / (float)MR;
        float v = q / (float)MR - m*m;
        smean[tid] = m; srstd[tid] = rsqrtf(v + EPSF);
    }
    __syncthreads();

    int row = blockIdx.x * 256 + tid;
    float xv[35];
    if (layer0) {
        int i = row >> 7, j = row & 127;
        #pragma unroll
        for (int c = 0; c < 35; c++)
            xv[c] = fmaxf(fabsf(featS[i*35 + c] - featS[j*35 + c]), 1e-6f);
    } else {
        #pragma unroll
        for (int c = 0; c < 35; c++)
            xv[c] = fmaxf((xin[(size_t)row*35 + c] - smean[c]) * srstd[c], 0.f);
    }
    float acc[35];
    #pragma unroll
    for (int c = 0; c < 35; c++) acc[c] = 0.f;
    for (int c = 0; c < 35; c++) {
        float xa = xv[c];
        const float* wr = Ws + c*35;
        #pragma unroll
        for (int c2 = 0; c2 < 35; c2++) acc[c2] = fmaf(xa, wr[c2], acc[c2]);
    }
    #pragma unroll
    for (int c = 0; c < 35; c++) yout[(size_t)row*35 + c] = acc[c];

    int lane = tid & 31, warp = tid >> 5;
    for (int c = 0; c < 35; c++) {
        float s = acc[c]; float q = s * s;
        #pragma unroll
        for (int o = 16; o; o >>= 1) {
            s += __shfl_down_sync(0xffffffffu, s, o);
            q += __shfl_down_sync(0xffffffffu, q, o);
        }
        if (lane == 0) { ps[warp][c] = s; ps[warp][35 + c] = q; }
    }
    __syncthreads();
    if (tid < 70) {
        float t = 0.f;
        #pragma unroll
        for (int w = 0; w < 8; w++) t += ps[w][tid];
        int target = (tid < 35) ? tid : (64 + tid - 35);
        atomicAdd(&ostats[target], t);
    }
}

// ---------------- merge output ----------------
__global__ __launch_bounds__(256, 1)
void merge_out_kernel(const float* __restrict__ xin,
                      const float* __restrict__ Wgo, const float* __restrict__ bgo,
                      const float* __restrict__ pstats,
                      float* __restrict__ out, int N) {
    __shared__ float wout[35];
    __shared__ float smean[35], srstd[35];
    int tid = threadIdx.x;
    if (tid < 35) {
        wout[tid] = Wgo[tid];
        float s = pstats[tid], q = pstats[64 + tid];
        float m = s / (float)MR;
        float v = q / (float)MR - m*m;
        smean[tid] = m; srstd[tid] = rsqrtf(v + EPSF);
    }
    __syncthreads();
    int row = blockIdx.x * 256 + tid;
    int i = row >> 7, j = row & 127;
    float acc = bgo[0];
    #pragma unroll
    for (int c = 0; c < 35; c++) {
        float x = fmaxf((xin[(size_t)row*35 + c] - smean[c]) * srstd[c], 0.f);
        acc = fmaf(x, wout[c], acc);
    }
    float v = (g_cb[i] != g_cb[j]) ? 0.f : sigmoidf_(acc);
    out[(size_t)i * ((size_t)N + IC) + (size_t)N + j] = v;
}

// ---------------- launch ----------------
extern "C" void kernel_launch(void* const* d_in, const int* in_sizes, int n_in,
                              void* d_out, int out_size) {
    const float* output_feats = (const float*)d_in[0];
    const float* coords       = (const float*)d_in[1];
    const float* heat         = (const float*)d_in[2];
    const int*   batch_idxs   = (const int*)  d_in[3];
    const float* Wm           = (const float*)d_in[4];
    const float* Wm_out       = (const float*)d_in[5];
    const float* bm_out       = (const float*)d_in[6];
    const float* Wk           = (const float*)d_in[7];
    const float* Wk_out       = (const float*)d_in[8];
    const float* bk_out       = (const float*)d_in[9];
    const float* Wg           = (const float*)d_in[10];
    const float* Wg_out       = (const float*)d_in[11];
    const float* bg_out       = (const float*)d_in[12];
    const float* Wwg          = (const float*)d_in[13];
    const float* bwg          = (const float*)d_in[14];
    float* out = (float*)d_out;
    int N = in_sizes[2];

    float *yA, *yB, *mA, *mB, *stats, *mstats;
    cudaGetSymbolAddress((void**)&yA, g_yA);
    cudaGetSymbolAddress((void**)&yB, g_yB);
    cudaGetSymbolAddress((void**)&mA, g_mA);
    cudaGetSymbolAddress((void**)&mB, g_mB);
    cudaGetSymbolAddress((void**)&stats, g_stats);
    cudaGetSymbolAddress((void**)&mstats, g_mstats);

    init_kernel<<<1, 384>>>();
    nms_kernel<<<NB, 1024>>>(heat, coords, batch_idxs, N);

    int tg = (N + 255) / 256;
    tower_layer_kernel<<<tg, 256>>>(output_feats, yA, Wm,        Wk,        nullptr,     N, 1);
    colstats_kernel<<<512, 256>>>(yA, stats, N);
    tower_layer_kernel<<<tg, 256>>>(yA,           yB, Wm + 1024, Wk + 1024, stats,       N, 0);
    colstats_kernel<<<512, 256>>>(yB, stats + 128, N);
    tower_layer_kernel<<<tg, 256>>>(yB,           yA, Wm + 2048, Wk + 2048, stats + 128, N, 0);
    colstats_kernel<<<512, 256>>>(yA, stats + 256, N);
    feats_kernel<<<tg, 256>>>(yA, Wm_out, bm_out, Wk_out, bk_out, stats + 256, N);

    cand_prep_kernel<<<IC, 352>>>(coords, batch_idxs, Wwg, bwg);

    dim3 mg((N + 255) / 256, 4);
    masks_kernel<<<mg, 128>>>(coords, out, N);

    merge_layer_kernel<<<64, 256>>>(nullptr, mA, Wg,        nullptr,      mstats,       1);
    merge_layer_kernel<<<64, 256>>>(mA,      mB, Wg + 1225, mstats,       mstats + 128, 0);
    merge_layer_kernel<<<64, 256>>>(mB,      mA, Wg + 2450, mstats + 128, mstats + 256, 0);
    merge_out_kernel<<<64, 256>>>(mA, Wg_out, bg_out, mstats + 256, out, N);
}